// round 13
// baseline (speedup 1.0000x reference)
#include <cuda_runtime.h>
#include <cstdint>

// LoKr: y = x @ kron(w1^T, w2^T) * (alpha/r),  x: (8192, 4096) fp32
//   P[j,n] = sum_m w1b[m,j] X[m,n]; C[j,t] = sum_n P[j,n] w2b[n,t]
//   Q[l,t] = S*sum_j w1a[j,l] C[j,t]; Y[l,k] = sum_t Q[l,t] w2a[t,k]
// 4 rows per CTA iteration; each row owned by ONE warp pair (64 threads);
// all phase syncs pair-local named barriers (4 independent pipelines).
// Pairs 0-1: X staged via cp.async. Pairs 2-3: X direct via __ldg.
// 3 CTAs/SM (68KB smem, 85-reg cap) for latency hiding.

static constexpr float SCALING = 1.0f / 16.0f;

__device__ __forceinline__ float2 ffma2(float2 a, float2 b, float2 c) {
    float2 d;
    asm("{\n\t"
        ".reg .b64 ra, rb, rc, rd;\n\t"
        "mov.b64 ra, {%2,%3};\n\t"
        "mov.b64 rb, {%4,%5};\n\t"
        "mov.b64 rc, {%6,%7};\n\t"
        "fma.rn.f32x2 rd, ra, rb, rc;\n\t"
        "mov.b64 {%0,%1}, rd;\n\t"
        "}"
        : "=f"(d.x), "=f"(d.y)
        : "f"(a.x), "f"(a.y), "f"(b.x), "f"(b.y), "f"(c.x), "f"(c.y));
    return d;
}

// Dynamic smem (float offsets):
//   X     [0, 8192)       r*4096 (r=0,1 only): staged X rows
//   PQC   [8192, 14336)   r*1536: P (stride 68) in [0,1088);
//                         Q (stride 20) in [0,1280) (after P dies);
//                         C dense [j*16+t] in [1280,1536) -- disjoint from
//                         P reads (step2) and Q writes (step3).
//   w1bp  [14336, 15360)  float4[256] [m*4+jg] = {w1b[m][jg],[+4],[+8],[+12]}
//   w2b4  [15360, 16384)  float4[256] [n*4+tg] = w2b[n][4tg..4tg+3]
//   w2a   [16384, 17408)  row-major [t*64+k]
static constexpr int SMEM_FLOATS = 17408;
static constexpr int SMEM_BYTES  = SMEM_FLOATS * 4;   // 69632 B -> 3 CTAs/SM

#define PAIR_BAR() asm volatile("bar.sync %0, 64;" :: "r"(r + 1) : "memory")

__global__ void __launch_bounds__(256, 3) lokr_fused(
    const float* __restrict__ x,
    const float* __restrict__ w1a, const float* __restrict__ w1b,
    const float* __restrict__ w2a, const float* __restrict__ w2b,
    float* __restrict__ out, int rows)
{
    extern __shared__ __align__(16) float smem[];
    const int tid = threadIdx.x;
    const int r   = tid >> 6;        // pair id / row-sub 0..3
    const int s   = tid & 63;        // lane within pair

    float*  Xrow   = smem + r * 4096;              // valid only for r < 2
    float*  PQ     = smem + 8192 + r * 1536;
    float4* w1bp_s = reinterpret_cast<float4*>(smem + 14336);
    float4* w2b4_s = reinterpret_cast<float4*>(smem + 15360);
    float*  w2a_s  = smem + 16384;

    // ---- one-time weight setup (CTA-wide) ----
    {
        int m = tid >> 2, jg = tid & 3;
        w1bp_s[tid] = make_float4(w1b[m * 16 + jg],
                                  w1b[m * 16 + jg + 4],
                                  w1b[m * 16 + jg + 8],
                                  w1b[m * 16 + jg + 12]);
        w2b4_s[tid] = reinterpret_cast<const float4*>(w2b)[tid];
        reinterpret_cast<float4*>(w2a_s)[tid] = reinterpret_cast<const float4*>(w2a)[tid];
    }
    float wa_col[16];                 // S * w1a[:, l=s] for step 3
#pragma unroll
    for (int j = 0; j < 16; j++) wa_col[j] = SCALING * w1a[j * 64 + s];
    __syncthreads();                  // weights visible to all pairs

    const int nIter = (rows + 3) >> 2;
    const int ng = s >> 2, jg = s & 3, n0 = ng * 4;

    // Stage this pair's X row via cp.async -- pairs 0-1 only (16 x 16B).
    auto issue_stage = [&](int it) {
        if (r < 2 && it < nIter && it * 4 + r < rows) {
            const float4* src = reinterpret_cast<const float4*>(x)
                              + (size_t)(it * 4 + r) * 1024;
            float4* dst = reinterpret_cast<float4*>(Xrow);
#pragma unroll
            for (int i = 0; i < 16; i++) {
                uint32_t sa = (uint32_t)__cvta_generic_to_shared(dst + s + 64 * i);
                asm volatile("cp.async.cg.shared.global [%0], [%1], 16;"
                             :: "r"(sa), "l"(src + s + 64 * i));
            }
        }
        asm volatile("cp.async.commit_group;");   // harmless empty group r>=2
    };

    int iter = blockIdx.x;
    issue_stage(iter);                // prologue

    for (; iter < nIter; iter += gridDim.x) {
        const int  my_row = iter * 4 + r;
        const bool valid  = (my_row < rows);

        asm volatile("cp.async.wait_group 0;" ::: "memory");
        PAIR_BAR();                   // bar A: X visible (r<2); prev Q reads done

        // ---- Step 1: P[j,n] = sum_m w1b[m,j] X[m,n] ----
        {
            float2 a0 = make_float2(0.f, 0.f), a1 = make_float2(0.f, 0.f);
            float2 a2 = make_float2(0.f, 0.f), a3 = make_float2(0.f, 0.f);
            float2 a4 = make_float2(0.f, 0.f), a5 = make_float2(0.f, 0.f);
            float2 a6 = make_float2(0.f, 0.f), a7 = make_float2(0.f, 0.f);
            if (r < 2) {              // staged rows: smem X (warp-broadcast lines)
#pragma unroll 8
                for (int m = 0; m < 64; m++) {
                    float4 X4 = *reinterpret_cast<const float4*>(Xrow + m * 64 + n0);
                    float4 W4 = w1bp_s[m * 4 + jg];
                    float2 xa = make_float2(X4.x, X4.y), xb = make_float2(X4.z, X4.w);
                    a0 = ffma2(make_float2(W4.x, W4.x), xa, a0);
                    a1 = ffma2(make_float2(W4.x, W4.x), xb, a1);
                    a2 = ffma2(make_float2(W4.y, W4.y), xa, a2);
                    a3 = ffma2(make_float2(W4.y, W4.y), xb, a3);
                    a4 = ffma2(make_float2(W4.z, W4.z), xa, a4);
                    a5 = ffma2(make_float2(W4.z, W4.z), xb, a5);
                    a6 = ffma2(make_float2(W4.w, W4.w), xa, a6);
                    a7 = ffma2(make_float2(W4.w, W4.w), xb, a7);
                }
            } else if (valid) {       // direct rows: one 128B line per warp per m
                const float4* xr = reinterpret_cast<const float4*>(x)
                                 + (size_t)my_row * 1024;
#pragma unroll 8
                for (int m = 0; m < 64; m++) {
                    float4 X4 = __ldg(xr + m * 16 + ng);
                    float4 W4 = w1bp_s[m * 4 + jg];
                    float2 xa = make_float2(X4.x, X4.y), xb = make_float2(X4.z, X4.w);
                    a0 = ffma2(make_float2(W4.x, W4.x), xa, a0);
                    a1 = ffma2(make_float2(W4.x, W4.x), xb, a1);
                    a2 = ffma2(make_float2(W4.y, W4.y), xa, a2);
                    a3 = ffma2(make_float2(W4.y, W4.y), xb, a3);
                    a4 = ffma2(make_float2(W4.z, W4.z), xa, a4);
                    a5 = ffma2(make_float2(W4.z, W4.z), xb, a5);
                    a6 = ffma2(make_float2(W4.w, W4.w), xa, a6);
                    a7 = ffma2(make_float2(W4.w, W4.w), xb, a7);
                }
            }
            // P store (stride 68). Overwrites prev Q -- readers behind bar A.
            *reinterpret_cast<float4*>(PQ + (jg     ) * 68 + n0) = make_float4(a0.x, a0.y, a1.x, a1.y);
            *reinterpret_cast<float4*>(PQ + (jg +  4) * 68 + n0) = make_float4(a2.x, a2.y, a3.x, a3.y);
            *reinterpret_cast<float4*>(PQ + (jg +  8) * 68 + n0) = make_float4(a4.x, a4.y, a5.x, a5.y);
            *reinterpret_cast<float4*>(PQ + (jg + 12) * 68 + n0) = make_float4(a6.x, a6.y, a7.x, a7.y);
        }
        PAIR_BAR();                   // bar B: P visible; X reads done

        // Prefetch next iteration's X (pairs 0-1; X dead).
        issue_stage(iter + gridDim.x);

        // ---- Step 2: C[j,t] = sum_n P[j,n] w2b[n,t] ----
        // reads P [0,1088), writes C [1280,1536) -- disjoint, no race.
        {
            const int j = s >> 2, tg = s & 3;
            const float* Pr = PQ + j * 68;     // stride 68: conflict-free
            float2 c01 = make_float2(0.f, 0.f), c23 = make_float2(0.f, 0.f);
#pragma unroll
            for (int nb = 0; nb < 16; nb++) {
                float4 P4  = *reinterpret_cast<const float4*>(Pr + nb * 4);
                float4 Wn0 = w2b4_s[(nb * 4 + 0) * 4 + tg];
                float4 Wn1 = w2b4_s[(nb * 4 + 1) * 4 + tg];
                float4 Wn2 = w2b4_s[(nb * 4 + 2) * 4 + tg];
                float4 Wn3 = w2b4_s[(nb * 4 + 3) * 4 + tg];
                c01 = ffma2(make_float2(P4.x, P4.x), make_float2(Wn0.x, Wn0.y), c01);
                c23 = ffma2(make_float2(P4.x, P4.x), make_float2(Wn0.z, Wn0.w), c23);
                c01 = ffma2(make_float2(P4.y, P4.y), make_float2(Wn1.x, Wn1.y), c01);
                c23 = ffma2(make_float2(P4.y, P4.y), make_float2(Wn1.z, Wn1.w), c23);
                c01 = ffma2(make_float2(P4.z, P4.z), make_float2(Wn2.x, Wn2.y), c01);
                c23 = ffma2(make_float2(P4.z, P4.z), make_float2(Wn2.z, Wn2.w), c23);
                c01 = ffma2(make_float2(P4.w, P4.w), make_float2(Wn3.x, Wn3.y), c01);
                c23 = ffma2(make_float2(P4.w, P4.w), make_float2(Wn3.z, Wn3.w), c23);
            }
            // dense C: [1280 + j*16 + t], max write end 1535 < 1536 (in range)
            *reinterpret_cast<float4*>(PQ + 1280 + j * 16 + tg * 4) =
                make_float4(c01.x, c01.y, c23.x, c23.y);
        }
        PAIR_BAR();                   // bar C: C visible; P reads done

        // ---- Step 3: Q[l,t] = S * sum_j w1a[j,l] C[j,t] ----
        // reads C [1280,1536), writes Q [0,1280) (P dead) -- disjoint.
        {
            const int l = s;
            float2 q[8];
#pragma unroll
            for (int i = 0; i < 8; i++) q[i] = make_float2(0.f, 0.f);
#pragma unroll
            for (int j = 0; j < 16; j++) {
                float2 wd = make_float2(wa_col[j], wa_col[j]);
#pragma unroll
                for (int u = 0; u < 4; u++) {
                    float4 cv = *reinterpret_cast<const float4*>(PQ + 1280 + j * 16 + u * 4);
                    q[2 * u]     = ffma2(wd, make_float2(cv.x, cv.y), q[2 * u]);
                    q[2 * u + 1] = ffma2(wd, make_float2(cv.z, cv.w), q[2 * u + 1]);
                }
            }
            float* Qr = PQ + l * 20;
#pragma unroll
            for (int u = 0; u < 4; u++)
                *reinterpret_cast<float4*>(Qr + 4 * u) =
                    make_float4(q[2 * u].x, q[2 * u].y, q[2 * u + 1].x, q[2 * u + 1].y);
        }
        PAIR_BAR();                   // bar D: Q visible

        // ---- Step 4: Y[l,k] = sum_t Q[l,t] w2a[t,k] ----
        {
            const int kq = s & 15, lg = s >> 4;
            const int k0 = kq * 4;
            float* orow = out + (size_t)my_row * 4096;
#pragma unroll 4
            for (int i = 0; i < 16; i++) {
                const int l = lg + 4 * i;
                const float4* Q4 = reinterpret_cast<const float4*>(PQ + l * 20);
                float2 a01 = make_float2(0.f, 0.f), a23 = make_float2(0.f, 0.f);
#pragma unroll
                for (int u = 0; u < 4; u++) {
                    float4 qv = Q4[u];
                    float4 w;
                    w = *reinterpret_cast<const float4*>(&w2a_s[(4 * u + 0) * 64 + k0]);
                    a01 = ffma2(make_float2(qv.x, qv.x), make_float2(w.x, w.y), a01);
                    a23 = ffma2(make_float2(qv.x, qv.x), make_float2(w.z, w.w), a23);
                    w = *reinterpret_cast<const float4*>(&w2a_s[(4 * u + 1) * 64 + k0]);
                    a01 = ffma2(make_float2(qv.y, qv.y), make_float2(w.x, w.y), a01);
                    a23 = ffma2(make_float2(qv.y, qv.y), make_float2(w.z, w.w), a23);
                    w = *reinterpret_cast<const float4*>(&w2a_s[(4 * u + 2) * 64 + k0]);
                    a01 = ffma2(make_float2(qv.z, qv.z), make_float2(w.x, w.y), a01);
                    a23 = ffma2(make_float2(qv.z, qv.z), make_float2(w.z, w.w), a23);
                    w = *reinterpret_cast<const float4*>(&w2a_s[(4 * u + 3) * 64 + k0]);
                    a01 = ffma2(make_float2(qv.w, qv.w), make_float2(w.x, w.y), a01);
                    a23 = ffma2(make_float2(qv.w, qv.w), make_float2(w.z, w.w), a23);
                }
                if (valid)
                    *reinterpret_cast<float4*>(orow + l * 64 + k0) =
                        make_float4(a01.x, a01.y, a23.x, a23.y);
            }
        }
        // Next iter's bar A orders step-4 Q reads vs. next P store.
    }
}

extern "C" void kernel_launch(void* const* d_in, const int* in_sizes, int n_in,
                              void* d_out, int out_size) {
    const float* x   = (const float*)d_in[0];
    const float* w1a = (const float*)d_in[1];
    const float* w1b = (const float*)d_in[2];
    const float* w2a = (const float*)d_in[3];
    const float* w2b = (const float*)d_in[4];
    float* out = (float*)d_out;

    int rows = in_sizes[0] / 4096;
    int nIter = (rows + 3) >> 2;

    cudaFuncSetAttribute(lokr_fused, cudaFuncAttributeMaxDynamicSharedMemorySize,
                         SMEM_BYTES);
    int grid = nIter < 444 ? nIter : 444;   // 148 SMs x 3 CTAs
    lokr_fused<<<grid, 256, SMEM_BYTES>>>(x, w1a, w1b, w2a, w2b, out, rows);
}

// round 14
// speedup vs baseline: 1.4018x; 1.4018x over previous
#include <cuda_runtime.h>
#include <cstdint>

// LoKr: y = x @ kron(w1^T, w2^T) * (alpha/r),  x: (8192, 4096) fp32
//   P[j,n] = sum_m w1b[m,j] X[m,n]; C[j,t] = sum_n P[j,n] w2b[n,t]
//   Q[l,t] = S*sum_j w1a[j,l] C[j,t]; Y[l,k] = sum_t Q[l,t] w2a[t,k]
// 4 rows per CTA iteration; each row owned by ONE warp pair (64 threads);
// all phase syncs pair-local named barriers (4 independent pipelines).
// All X staged via cp.async (R12 structure -- direct-ldg variants are
// triply falsified). Step-4 w2a held in 16 float4 REGISTERS (loop-invariant).

static constexpr float SCALING = 1.0f / 16.0f;

__device__ __forceinline__ float2 ffma2(float2 a, float2 b, float2 c) {
    float2 d;
    asm("{\n\t"
        ".reg .b64 ra, rb, rc, rd;\n\t"
        "mov.b64 ra, {%2,%3};\n\t"
        "mov.b64 rb, {%4,%5};\n\t"
        "mov.b64 rc, {%6,%7};\n\t"
        "fma.rn.f32x2 rd, ra, rb, rc;\n\t"
        "mov.b64 {%0,%1}, rd;\n\t"
        "}"
        : "=f"(d.x), "=f"(d.y)
        : "f"(a.x), "f"(a.y), "f"(b.x), "f"(b.y), "f"(c.x), "f"(c.y));
    return d;
}

// Dynamic smem (float offsets):
//   X     [0, 16384)      r*4096  : X row r (own region, only cp.async writes)
//   PQC   [16384, 22528)  r*1536  : P (stride 68) in [0,1088);
//                                   Q (stride 20) in [0,1280) (after P dies);
//                                   C dense [j*16+t] in [1280,1536) -- disjoint
//                                   from P reads (step2) and Q writes (step3).
//   w1bp  [22528, 23552)  float4[256] [m*4+jg] = {w1b[m][jg],[+4],[+8],[+12]}
//   w2b4  [23552, 24576)  float4[256] [n*4+tg] = w2b[n][4tg..4tg+3]
static constexpr int SMEM_FLOATS = 24576;
static constexpr int SMEM_BYTES  = SMEM_FLOATS * 4;   // 98304 B -> 2 CTAs/SM

#define PAIR_BAR() asm volatile("bar.sync %0, 64;" :: "r"(r + 1) : "memory")

__global__ void __launch_bounds__(256, 2) lokr_fused(
    const float* __restrict__ x,
    const float* __restrict__ w1a, const float* __restrict__ w1b,
    const float* __restrict__ w2a, const float* __restrict__ w2b,
    float* __restrict__ out, int rows)
{
    extern __shared__ __align__(16) float smem[];
    const int tid = threadIdx.x;
    const int r   = tid >> 6;        // pair id / row-sub 0..3
    const int s   = tid & 63;        // lane within pair

    float*  Xrow   = smem + r * 4096;
    float*  PQ     = smem + 16384 + r * 1536;
    float4* w1bp_s = reinterpret_cast<float4*>(smem + 22528);
    float4* w2b4_s = reinterpret_cast<float4*>(smem + 23552);

    // ---- one-time weight setup (CTA-wide) ----
    {
        int m = tid >> 2, jg = tid & 3;
        w1bp_s[tid] = make_float4(w1b[m * 16 + jg],
                                  w1b[m * 16 + jg + 4],
                                  w1b[m * 16 + jg + 8],
                                  w1b[m * 16 + jg + 12]);
        w2b4_s[tid] = reinterpret_cast<const float4*>(w2b)[tid];
    }
    float wa_col[16];                 // S * w1a[:, l=s] for step 3
#pragma unroll
    for (int j = 0; j < 16; j++) wa_col[j] = SCALING * w1a[j * 64 + s];

    // Step-4 w2a panel: thread's k0 = 4*(s&15) is fixed -> 16 float4, loop-invariant.
    float4 Wreg[16];
    {
        const int k0 = (s & 15) * 4;
#pragma unroll
        for (int t = 0; t < 16; t++)
            Wreg[t] = *reinterpret_cast<const float4*>(w2a + t * 64 + k0);
    }
    __syncthreads();                  // weights visible to all pairs

    const int nIter = (rows + 3) >> 2;
    const int ng = s >> 2, jg = s & 3, n0 = ng * 4;

    // Stage this pair's X row for iteration `it` via cp.async (16 x 16B).
    auto issue_stage = [&](int it) {
        if (it < nIter && it * 4 + r < rows) {
            const float4* src = reinterpret_cast<const float4*>(x)
                              + (size_t)(it * 4 + r) * 1024;
            float4* dst = reinterpret_cast<float4*>(Xrow);
#pragma unroll
            for (int i = 0; i < 16; i++) {
                uint32_t sa = (uint32_t)__cvta_generic_to_shared(dst + s + 64 * i);
                asm volatile("cp.async.cg.shared.global [%0], [%1], 16;"
                             :: "r"(sa), "l"(src + s + 64 * i));
            }
        }
        asm volatile("cp.async.commit_group;");
    };

    int iter = blockIdx.x;
    issue_stage(iter);                // prologue

    for (; iter < nIter; iter += gridDim.x) {
        const int  my_row = iter * 4 + r;
        const bool valid  = (my_row < rows);

        asm volatile("cp.async.wait_group 0;" ::: "memory");
        PAIR_BAR();                   // bar A: X visible; prev-iter Q reads done

        // ---- Step 1: P[j,n] = sum_m w1b[m,j] X[m,n] ----
        {
            float2 a0 = make_float2(0.f, 0.f), a1 = make_float2(0.f, 0.f);
            float2 a2 = make_float2(0.f, 0.f), a3 = make_float2(0.f, 0.f);
            float2 a4 = make_float2(0.f, 0.f), a5 = make_float2(0.f, 0.f);
            float2 a6 = make_float2(0.f, 0.f), a7 = make_float2(0.f, 0.f);
#pragma unroll 8
            for (int m = 0; m < 64; m++) {
                float4 X4 = *reinterpret_cast<const float4*>(Xrow + m * 64 + n0);
                float4 W4 = w1bp_s[m * 4 + jg];
                float2 xa = make_float2(X4.x, X4.y), xb = make_float2(X4.z, X4.w);
                a0 = ffma2(make_float2(W4.x, W4.x), xa, a0);
                a1 = ffma2(make_float2(W4.x, W4.x), xb, a1);
                a2 = ffma2(make_float2(W4.y, W4.y), xa, a2);
                a3 = ffma2(make_float2(W4.y, W4.y), xb, a3);
                a4 = ffma2(make_float2(W4.z, W4.z), xa, a4);
                a5 = ffma2(make_float2(W4.z, W4.z), xb, a5);
                a6 = ffma2(make_float2(W4.w, W4.w), xa, a6);
                a7 = ffma2(make_float2(W4.w, W4.w), xb, a7);
            }
            // P store (stride 68). Overwrites prev Q -- readers behind bar A.
            *reinterpret_cast<float4*>(PQ + (jg     ) * 68 + n0) = make_float4(a0.x, a0.y, a1.x, a1.y);
            *reinterpret_cast<float4*>(PQ + (jg +  4) * 68 + n0) = make_float4(a2.x, a2.y, a3.x, a3.y);
            *reinterpret_cast<float4*>(PQ + (jg +  8) * 68 + n0) = make_float4(a4.x, a4.y, a5.x, a5.y);
            *reinterpret_cast<float4*>(PQ + (jg + 12) * 68 + n0) = make_float4(a6.x, a6.y, a7.x, a7.y);
        }
        PAIR_BAR();                   // bar B: P visible; X reads done

        // Prefetch next iteration's X (X dead; lands before next wait).
        issue_stage(iter + gridDim.x);

        // ---- Step 2: C[j,t] = sum_n P[j,n] w2b[n,t] ----
        // reads P [0,1088), writes C [1280,1536) -- disjoint, no race.
        {
            const int j = s >> 2, tg = s & 3;
            const float* Pr = PQ + j * 68;     // stride 68: conflict-free
            float2 c01 = make_float2(0.f, 0.f), c23 = make_float2(0.f, 0.f);
#pragma unroll
            for (int nb = 0; nb < 16; nb++) {
                float4 P4  = *reinterpret_cast<const float4*>(Pr + nb * 4);
                float4 Wn0 = w2b4_s[(nb * 4 + 0) * 4 + tg];
                float4 Wn1 = w2b4_s[(nb * 4 + 1) * 4 + tg];
                float4 Wn2 = w2b4_s[(nb * 4 + 2) * 4 + tg];
                float4 Wn3 = w2b4_s[(nb * 4 + 3) * 4 + tg];
                c01 = ffma2(make_float2(P4.x, P4.x), make_float2(Wn0.x, Wn0.y), c01);
                c23 = ffma2(make_float2(P4.x, P4.x), make_float2(Wn0.z, Wn0.w), c23);
                c01 = ffma2(make_float2(P4.y, P4.y), make_float2(Wn1.x, Wn1.y), c01);
                c23 = ffma2(make_float2(P4.y, P4.y), make_float2(Wn1.z, Wn1.w), c23);
                c01 = ffma2(make_float2(P4.z, P4.z), make_float2(Wn2.x, Wn2.y), c01);
                c23 = ffma2(make_float2(P4.z, P4.z), make_float2(Wn2.z, Wn2.w), c23);
                c01 = ffma2(make_float2(P4.w, P4.w), make_float2(Wn3.x, Wn3.y), c01);
                c23 = ffma2(make_float2(P4.w, P4.w), make_float2(Wn3.z, Wn3.w), c23);
            }
            // dense C: [1280 + j*16 + t], max write end 1535 < 1536 (in range)
            *reinterpret_cast<float4*>(PQ + 1280 + j * 16 + tg * 4) =
                make_float4(c01.x, c01.y, c23.x, c23.y);
        }
        PAIR_BAR();                   // bar C: C visible; P reads done

        // ---- Step 3: Q[l,t] = S * sum_j w1a[j,l] C[j,t] ----
        // reads C [1280,1536), writes Q [0,1280) (P dead) -- disjoint.
        {
            const int l = s;
            float2 q[8];
#pragma unroll
            for (int i = 0; i < 8; i++) q[i] = make_float2(0.f, 0.f);
#pragma unroll
            for (int j = 0; j < 16; j++) {
                float2 wd = make_float2(wa_col[j], wa_col[j]);
#pragma unroll
                for (int u = 0; u < 4; u++) {
                    float4 cv = *reinterpret_cast<const float4*>(PQ + 1280 + j * 16 + u * 4);
                    q[2 * u]     = ffma2(wd, make_float2(cv.x, cv.y), q[2 * u]);
                    q[2 * u + 1] = ffma2(wd, make_float2(cv.z, cv.w), q[2 * u + 1]);
                }
            }
            float* Qr = PQ + l * 20;
#pragma unroll
            for (int u = 0; u < 4; u++)
                *reinterpret_cast<float4*>(Qr + 4 * u) =
                    make_float4(q[2 * u].x, q[2 * u].y, q[2 * u + 1].x, q[2 * u + 1].y);
        }
        PAIR_BAR();                   // bar D: Q visible

        // ---- Step 4: Y[l,k] = sum_t Q[l,t] w2a[t,k]; w2a in REGISTERS ----
        {
            const int lg = s >> 4;
            const int k0 = (s & 15) * 4;
            float* orow = out + (size_t)my_row * 4096;
#pragma unroll 4
            for (int i = 0; i < 16; i++) {
                const int l = lg + 4 * i;
                const float4* Q4 = reinterpret_cast<const float4*>(PQ + l * 20);
                float2 a01 = make_float2(0.f, 0.f), a23 = make_float2(0.f, 0.f);
#pragma unroll
                for (int u = 0; u < 4; u++) {
                    float4 qv = Q4[u];
                    float4 w;
                    w = Wreg[4 * u + 0];
                    a01 = ffma2(make_float2(qv.x, qv.x), make_float2(w.x, w.y), a01);
                    a23 = ffma2(make_float2(qv.x, qv.x), make_float2(w.z, w.w), a23);
                    w = Wreg[4 * u + 1];
                    a01 = ffma2(make_float2(qv.y, qv.y), make_float2(w.x, w.y), a01);
                    a23 = ffma2(make_float2(qv.y, qv.y), make_float2(w.z, w.w), a23);
                    w = Wreg[4 * u + 2];
                    a01 = ffma2(make_float2(qv.z, qv.z), make_float2(w.x, w.y), a01);
                    a23 = ffma2(make_float2(qv.z, qv.z), make_float2(w.z, w.w), a23);
                    w = Wreg[4 * u + 3];
                    a01 = ffma2(make_float2(qv.w, qv.w), make_float2(w.x, w.y), a01);
                    a23 = ffma2(make_float2(qv.w, qv.w), make_float2(w.z, w.w), a23);
                }
                if (valid)
                    *reinterpret_cast<float4*>(orow + l * 64 + k0) =
                        make_float4(a01.x, a01.y, a23.x, a23.y);
            }
        }
        // Next iter's bar A orders step-4 Q reads vs. next P store.
    }
}

extern "C" void kernel_launch(void* const* d_in, const int* in_sizes, int n_in,
                              void* d_out, int out_size) {
    const float* x   = (const float*)d_in[0];
    const float* w1a = (const float*)d_in[1];
    const float* w1b = (const float*)d_in[2];
    const float* w2a = (const float*)d_in[3];
    const float* w2b = (const float*)d_in[4];
    float* out = (float*)d_out;

    int rows = in_sizes[0] / 4096;
    int nIter = (rows + 3) >> 2;

    cudaFuncSetAttribute(lokr_fused, cudaFuncAttributeMaxDynamicSharedMemorySize,
                         SMEM_BYTES);
    int grid = nIter < 296 ? nIter : 296;   // 148 SMs x 2 CTAs
    lokr_fused<<<grid, 256, SMEM_BYTES>>>(x, w1a, w1b, w2a, w2b, out, rows);
}